// round 4
// baseline (speedup 1.0000x reference)
#include <cuda_runtime.h>
#include <math.h>

#define NP 5
#define NH 64
#define NFEAT (2*NP + 2)

__global__ __launch_bounds__(256)
void topo_kernel(const float* __restrict__ pillars,
                 const float* __restrict__ W1,   // [P][H] row-major
                 const float* __restrict__ b1,   // [H]
                 const float* __restrict__ W2,   // [H]
                 const float* __restrict__ b2p,  // [1]
                 const float* __restrict__ ln_g, // [P]
                 const float* __restrict__ ln_b, // [P]
                 const float* __restrict__ Wc,   // [2P+2]
                 const float* __restrict__ bcp,  // [1]
                 float* __restrict__ out, int n)
{
    __shared__ float sW1[NP * NH];
    __shared__ float sb1[NH], sW2[NH], scn[NH];
    __shared__ float sg[NP], sbe[NP], sWc[NFEAT];
    __shared__ float sb2, sbc;

    const int t = threadIdx.x;
    // Strided staging: covers all 320 W1 elements regardless of blockDim.
    for (int k = t; k < NP * NH; k += blockDim.x) sW1[k] = W1[k];
    for (int k = t; k < NH; k += blockDim.x) { sb1[k] = b1[k]; sW2[k] = W2[k]; }
    if (t < NP) { sg[t] = ln_g[t]; sbe[t] = ln_b[t]; }
    if (t < NFEAT) sWc[t] = Wc[t];
    if (t == 0) { sb2 = b2p[0]; sbc = bcp[0]; }
    __syncthreads();
    if (t < NH) {
        float c = 0.f;
        #pragma unroll
        for (int j = 0; j < NP; j++) { float w = sW1[j * NH + t]; c += w * w; }
        scn[t] = c;
    }
    __syncthreads();

    const int i = blockIdx.x * blockDim.x + t;
    if (i >= n) return;

    // --- load + sanitize ---
    float raw[NP], p[NP];
    #pragma unroll
    for (int j = 0; j < NP; j++) {
        float v = pillars[i * NP + j];
        raw[j] = v;
        float c = isnan(v) ? 0.5f : v;          // nan_to_num(nan=0.5)
        p[j] = fminf(fmaxf(c, 0.f), 1.f);       // clip [0,1] (also kills +-inf)
    }

    // --- layernorm of p (biased var, eps 1e-5) ---
    float mu = 0.f;
    #pragma unroll
    for (int j = 0; j < NP; j++) mu += p[j];
    mu *= 0.2f;
    float var = 0.f;
    #pragma unroll
    for (int j = 0; j < NP; j++) { float d = p[j] - mu; var += d * d; }
    var *= 0.2f;
    float inv_std = rsqrtf(var + 1e-5f);
    float x[NP];
    #pragma unroll
    for (int j = 0; j < NP; j++) x[j] = (p[j] - mu) * inv_std * sg[j] + sbe[j];

    // --- fused hidden loop: V, grad, trace(Hessian) ---
    const float INV_SQRT2   = 0.70710678118654752f;
    const float INV_SQRT2PI = 0.39894228040143268f;
    float V = 0.f, tr = 0.f;
    float grad[NP] = {0.f, 0.f, 0.f, 0.f, 0.f};

    #pragma unroll 16
    for (int h = 0; h < NH; h++) {
        float w0 = sW1[0 * NH + h], w1 = sW1[1 * NH + h], w2 = sW1[2 * NH + h];
        float w3 = sW1[3 * NH + h], w4 = sW1[4 * NH + h];
        float bh = sb1[h];
        float z1 = bh + p[0]*w0 + p[1]*w1 + p[2]*w2 + p[3]*w3 + p[4]*w4;
        float z2 = bh + x[0]*w0 + x[1]*w1 + x[2]*w2 + x[3]*w3 + x[4]*w4;

        float Phi  = 0.5f * (1.0f + erff(z1 * INV_SQRT2));       // N(0,1) CDF
        float phi1 = INV_SQRT2PI * __expf(-0.5f * z1 * z1);      // N(0,1) PDF
        float w2h  = sW2[h];

        V += z1 * Phi * w2h;                                     // gelu(z1) * W2
        float s = (Phi + z1 * phi1) * w2h;                       // gelu'(z1) * W2
        grad[0] += w0 * s; grad[1] += w1 * s; grad[2] += w2 * s;
        grad[3] += w3 * s; grad[4] += w4 * s;

        float phi2 = INV_SQRT2PI * __expf(-0.5f * z2 * z2);
        tr += scn[h] * w2h * (phi2 * (2.0f - z2 * z2));          // gelu''(z2) * colnorm * W2
    }
    V += sb2;
    float emean = tr * 0.2f;   // mean eigenvalue == trace/P (symmetrize preserves trace)

    // --- features -> L2 normalize -> classifier -> sigmoid -> clamp ---
    float ss = V * V + emean * emean;
    #pragma unroll
    for (int j = 0; j < NP; j++) ss += raw[j] * raw[j] + grad[j] * grad[j];
    float invn = 1.0f / fmaxf(sqrtf(ss), 1e-12f);

    float dot = 0.f;
    #pragma unroll
    for (int j = 0; j < NP; j++) dot += raw[j]  * sWc[j];
    #pragma unroll
    for (int j = 0; j < NP; j++) dot += grad[j] * sWc[NP + j];
    dot += V * sWc[2 * NP] + emean * sWc[2 * NP + 1];
    float logit = sbc + dot * invn;

    float prob = 1.0f / (1.0f + __expf(-logit));
    out[i] = fminf(fmaxf(prob, 0.f), 1.f);
}

extern "C" void kernel_launch(void* const* d_in, const int* in_sizes, int n_in,
                              void* d_out, int out_size) {
    const float* pillars = (const float*)d_in[0];
    const float* W1      = (const float*)d_in[1];
    const float* b1      = (const float*)d_in[2];
    const float* W2      = (const float*)d_in[3];
    const float* b2      = (const float*)d_in[4];
    const float* ln_g    = (const float*)d_in[5];
    const float* ln_b    = (const float*)d_in[6];
    const float* Wc      = (const float*)d_in[7];
    const float* bc      = (const float*)d_in[8];
    float* out = (float*)d_out;
    int n = out_size;  // one output per sample
    int threads = 256;
    int blocks = (n + threads - 1) / threads;
    topo_kernel<<<blocks, threads>>>(pillars, W1, b1, W2, b2, ln_g, ln_b, Wc, bc, out, n);
}

// round 7
// speedup vs baseline: 1.4594x; 1.4594x over previous
#include <cuda_runtime.h>
#include <math.h>
#include <stdint.h>

#define NP 5
#define NH 64

typedef unsigned long long u64;

__device__ __forceinline__ u64 pk2(float lo, float hi) {
    u64 r; asm("mov.b64 %0,{%1,%2};" : "=l"(r) : "f"(lo), "f"(hi)); return r;
}
__device__ __forceinline__ void upk2(float& lo, float& hi, u64 v) {
    asm("mov.b64 {%0,%1},%2;" : "=f"(lo), "=f"(hi) : "l"(v));
}
__device__ __forceinline__ u64 f2fma(u64 a, u64 b, u64 c) {
    u64 r; asm("fma.rn.f32x2 %0,%1,%2,%3;" : "=l"(r) : "l"(a), "l"(b), "l"(c)); return r;
}
__device__ __forceinline__ u64 f2mul(u64 a, u64 b) {
    u64 r; asm("mul.rn.f32x2 %0,%1,%2;" : "=l"(r) : "l"(a), "l"(b)); return r;
}
__device__ __forceinline__ float ex2f(float x) {
    float r; asm("ex2.approx.ftz.f32 %0,%1;" : "=f"(r) : "f"(x)); return r;
}
__device__ __forceinline__ float rcpf(float x) {
    float r; asm("rcp.approx.ftz.f32 %0,%1;" : "=f"(r) : "f"(x)); return r;
}
__device__ __forceinline__ u64 f2ex2(u64 v) {
    float lo, hi; upk2(lo, hi, v); return pk2(ex2f(lo), ex2f(hi));
}
__device__ __forceinline__ u64 f2rcp(u64 v) {
    float lo, hi; upk2(lo, hi, v); return pk2(rcpf(lo), rcpf(hi));
}

__global__ __launch_bounds__(128)
void topo_kernel(const float* __restrict__ pillars,
                 const float* __restrict__ W1,   // [P][H]
                 const float* __restrict__ b1,
                 const float* __restrict__ W2,
                 const float* __restrict__ b2p,
                 const float* __restrict__ ln_g,
                 const float* __restrict__ ln_b,
                 const float* __restrict__ Wc,
                 const float* __restrict__ bcp,
                 float* __restrict__ out, int n)
{
    // per-h record: {w0,w0}{w1,w1}{w2,w2}{w3,w3}{w4,w4}{bh,bh}{w2h,w2h}{cs,cs} = 64B
    __shared__ __align__(16) float2 sw[NH * 8];
    __shared__ float sg[NP], sbe[NP], sWc[12];
    __shared__ float sb2, sbc;

    const int t = threadIdx.x;
    if (t < NH) {
        float w[NP]; float cn = 0.f;
        #pragma unroll
        for (int j = 0; j < NP; j++) { w[j] = W1[j * NH + t]; cn += w[j] * w[j]; }
        float w2h = W2[t], bh = b1[t];
        float cs = cn * w2h * 0.3989422804f;   // colnorm * W2 * 1/sqrt(2pi)
        float2* d = &sw[t * 8];
        #pragma unroll
        for (int j = 0; j < NP; j++) d[j] = make_float2(w[j], w[j]);
        d[5] = make_float2(bh, bh);
        d[6] = make_float2(w2h, w2h);
        d[7] = make_float2(cs, cs);
    }
    if (t < NP)  { sg[t] = ln_g[t]; sbe[t] = ln_b[t]; }
    if (t < 12)  sWc[t] = Wc[t];
    if (t == 0)  { sb2 = b2p[0]; sbc = bcp[0]; }
    __syncthreads();

    const int pairIdx = blockIdx.x * blockDim.x + t;
    const int i0 = 2 * pairIdx;
    if (i0 >= n) return;
    const int i1 = (i0 + 1 < n) ? (i0 + 1) : i0;   // tail: duplicate

    // --- load + sanitize (scalar, cheap) ---
    float rawA[NP], rawB[NP], pA[NP], pB[NP];
    #pragma unroll
    for (int j = 0; j < NP; j++) {
        float va = pillars[i0 * NP + j];
        float vb = pillars[i1 * NP + j];
        rawA[j] = va; rawB[j] = vb;
        float ca = isnan(va) ? 0.5f : va;
        float cb = isnan(vb) ? 0.5f : vb;
        pA[j] = fminf(fmaxf(ca, 0.f), 1.f);
        pB[j] = fminf(fmaxf(cb, 0.f), 1.f);
    }

    // --- layernorm (scalar per sample) ---
    float xA[NP], xB[NP];
    {
        float mu = 0.f; for (int j = 0; j < NP; j++) mu += pA[j]; mu *= 0.2f;
        float var = 0.f; for (int j = 0; j < NP; j++) { float d = pA[j] - mu; var += d * d; } var *= 0.2f;
        float is = rsqrtf(var + 1e-5f);
        #pragma unroll
        for (int j = 0; j < NP; j++) xA[j] = (pA[j] - mu) * is * sg[j] + sbe[j];
    }
    {
        float mu = 0.f; for (int j = 0; j < NP; j++) mu += pB[j]; mu *= 0.2f;
        float var = 0.f; for (int j = 0; j < NP; j++) { float d = pB[j] - mu; var += d * d; } var *= 0.2f;
        float is = rsqrtf(var + 1e-5f);
        #pragma unroll
        for (int j = 0; j < NP; j++) xB[j] = (pB[j] - mu) * is * sg[j] + sbe[j];
    }

    u64 p2[NP], x2[NP];
    #pragma unroll
    for (int j = 0; j < NP; j++) { p2[j] = pk2(pA[j], pB[j]); x2[j] = pk2(xA[j], xB[j]); }

    // packed constants
    const u64 C_NHL2E = pk2(-0.72134752044f, -0.72134752044f); // -log2(e)/2
    const u64 C_IS2PI = pk2(0.3989422804f, 0.3989422804f);     // 1/sqrt(2pi)
    const u64 C_ONE   = pk2(1.0f, 1.0f);
    const u64 C_HALF  = pk2(0.5f, 0.5f);
    const u64 C_TWO   = pk2(2.0f, 2.0f);
    const u64 C_NEG1  = pk2(-1.0f, -1.0f);
    const u64 C_PAS   = pk2(0.2316419f, 0.2316419f);           // A&S 26.2.17 p
    const u64 C_B5    = pk2(1.330274429f, 1.330274429f);
    const u64 C_B4    = pk2(-1.821255978f, -1.821255978f);
    const u64 C_B3    = pk2(1.781477937f, 1.781477937f);
    const u64 C_B2    = pk2(-0.356563782f, -0.356563782f);
    const u64 C_B1    = pk2(0.319381530f, 0.319381530f);
    const u64 M_ABS   = 0x7FFFFFFF7FFFFFFFull;
    const u64 M_SGN   = 0x8000000080000000ull;

    u64 V2 = pk2(0.f, 0.f), tr2 = V2;
    u64 g2[NP] = {V2, V2, V2, V2, V2};

    const ulonglong2* sp = reinterpret_cast<const ulonglong2*>(sw);

    #pragma unroll 8
    for (int h = 0; h < NH; h++) {
        ulonglong2 q01 = sp[h * 4 + 0];   // {w0,w0},{w1,w1}
        ulonglong2 q23 = sp[h * 4 + 1];   // {w2,w2},{w3,w3}
        ulonglong2 q45 = sp[h * 4 + 2];   // {w4,w4},{bh,bh}
        ulonglong2 q67 = sp[h * 4 + 3];   // {w2h,w2h},{cs,cs}

        u64 z1 = f2fma(p2[0], q01.x, q45.y);
        z1 = f2fma(p2[1], q01.y, z1);
        z1 = f2fma(p2[2], q23.x, z1);
        z1 = f2fma(p2[3], q23.y, z1);
        z1 = f2fma(p2[4], q45.x, z1);

        u64 z2 = f2fma(x2[0], q01.x, q45.y);
        z2 = f2fma(x2[1], q01.y, z2);
        z2 = f2fma(x2[2], q23.x, z2);
        z2 = f2fma(x2[3], q23.y, z2);
        z2 = f2fma(x2[4], q45.x, z2);

        u64 sq1  = f2mul(z1, z1);
        u64 e1   = f2ex2(f2mul(sq1, C_NHL2E));    // exp(-z1^2/2)
        u64 phi1 = f2mul(e1, C_IS2PI);            // N(0,1) pdf at z1

        u64 sq2  = f2mul(z2, z2);
        u64 e2   = f2ex2(f2mul(sq2, C_NHL2E));    // exp(-z2^2/2)

        // Phi(z1) via A&S 26.2.17 (|err| < 7.5e-8), branchless sign
        u64 az  = z1 & M_ABS;
        u64 tt  = f2rcp(f2fma(az, C_PAS, C_ONE)); // t = 1/(1+p|z|)
        u64 Q   = f2fma(C_B5, tt, C_B4);
        Q = f2fma(Q, tt, C_B3);
        Q = f2fma(Q, tt, C_B2);
        Q = f2fma(Q, tt, C_B1);
        Q = f2mul(Q, tt);
        u64 G   = f2mul(phi1, Q);                 // 1 - Phi(|z|)
        u64 uu  = f2fma(G, C_NEG1, C_HALF);       // 0.5 - G
        u64 pm1 = C_ONE ^ (z1 & M_SGN);           // +-1.0 by sign(z1)
        u64 Phi = f2fma(pm1, uu, C_HALF);         // z>=0: 1-G ; z<0: G

        // V += gelu(z1)*w2h
        u64 zPhi = f2mul(z1, Phi);
        V2 = f2fma(zPhi, q67.x, V2);

        // s = gelu'(z1)*w2h = (Phi + z1*phi1)*w2h
        u64 s = f2fma(z1, phi1, Phi);
        s = f2mul(s, q67.x);
        g2[0] = f2fma(q01.x, s, g2[0]);
        g2[1] = f2fma(q01.y, s, g2[1]);
        g2[2] = f2fma(q23.x, s, g2[2]);
        g2[3] = f2fma(q23.y, s, g2[3]);
        g2[4] = f2fma(q45.x, s, g2[4]);

        // tr += cs * e2 * (2 - z2^2)   (cs = colnorm*W2/sqrt(2pi))
        u64 tm = f2fma(sq2, C_NEG1, C_TWO);
        tm = f2mul(e2, tm);
        tr2 = f2fma(q67.y, tm, tr2);
    }

    // --- epilogue (scalar per sample) ---
    float Va, Vb, tra, trb, ga[NP], gb[NP];
    upk2(Va, Vb, V2); upk2(tra, trb, tr2);
    #pragma unroll
    for (int j = 0; j < NP; j++) upk2(ga[j], gb[j], g2[j]);
    Va += sb2; Vb += sb2;
    float ema = tra * 0.2f, emb = trb * 0.2f;

    {
        float ss = Va * Va + ema * ema;
        #pragma unroll
        for (int j = 0; j < NP; j++) ss += rawA[j] * rawA[j] + ga[j] * ga[j];
        float invn = 1.0f / fmaxf(sqrtf(ss), 1e-12f);
        float dot = 0.f;
        #pragma unroll
        for (int j = 0; j < NP; j++) dot += rawA[j] * sWc[j];
        #pragma unroll
        for (int j = 0; j < NP; j++) dot += ga[j] * sWc[NP + j];
        dot += Va * sWc[10] + ema * sWc[11];
        float logit = sbc + dot * invn;
        float prob = 1.0f / (1.0f + __expf(-logit));
        out[i0] = fminf(fmaxf(prob, 0.f), 1.f);
    }
    if (i0 + 1 < n) {
        float ss = Vb * Vb + emb * emb;
        #pragma unroll
        for (int j = 0; j < NP; j++) ss += rawB[j] * rawB[j] + gb[j] * gb[j];
        float invn = 1.0f / fmaxf(sqrtf(ss), 1e-12f);
        float dot = 0.f;
        #pragma unroll
        for (int j = 0; j < NP; j++) dot += rawB[j] * sWc[j];
        #pragma unroll
        for (int j = 0; j < NP; j++) dot += gb[j] * sWc[NP + j];
        dot += Vb * sWc[10] + emb * sWc[11];
        float logit = sbc + dot * invn;
        float prob = 1.0f / (1.0f + __expf(-logit));
        out[i0 + 1] = fminf(fmaxf(prob, 0.f), 1.f);
    }
}

extern "C" void kernel_launch(void* const* d_in, const int* in_sizes, int n_in,
                              void* d_out, int out_size) {
    const float* pillars = (const float*)d_in[0];
    const float* W1      = (const float*)d_in[1];
    const float* b1      = (const float*)d_in[2];
    const float* W2      = (const float*)d_in[3];
    const float* b2      = (const float*)d_in[4];
    const float* ln_g    = (const float*)d_in[5];
    const float* ln_b    = (const float*)d_in[6];
    const float* Wc      = (const float*)d_in[7];
    const float* bc      = (const float*)d_in[8];
    float* out = (float*)d_out;
    int n = out_size;
    int pairs = (n + 1) / 2;
    int threads = 128;
    int blocks = (pairs + threads - 1) / threads;
    topo_kernel<<<blocks, threads>>>(pillars, W1, b1, W2, b2, ln_g, ln_b, Wc, bc, out, n);
}

// round 8
// speedup vs baseline: 1.6977x; 1.1633x over previous
#include <cuda_runtime.h>
#include <math.h>
#include <stdint.h>

#define NP 5
#define NH 64

typedef unsigned long long u64;

__device__ __forceinline__ u64 pk2(float lo, float hi) {
    u64 r; asm("mov.b64 %0,{%1,%2};" : "=l"(r) : "f"(lo), "f"(hi)); return r;
}
__device__ __forceinline__ void upk2(float& lo, float& hi, u64 v) {
    asm("mov.b64 {%0,%1},%2;" : "=f"(lo), "=f"(hi) : "l"(v));
}
__device__ __forceinline__ u64 f2fma(u64 a, u64 b, u64 c) {
    u64 r; asm("fma.rn.f32x2 %0,%1,%2,%3;" : "=l"(r) : "l"(a), "l"(b), "l"(c)); return r;
}
__device__ __forceinline__ u64 f2mul(u64 a, u64 b) {
    u64 r; asm("mul.rn.f32x2 %0,%1,%2;" : "=l"(r) : "l"(a), "l"(b)); return r;
}
__device__ __forceinline__ float ex2f(float x) {
    float r; asm("ex2.approx.ftz.f32 %0,%1;" : "=f"(r) : "f"(x)); return r;
}
__device__ __forceinline__ float tanhf_a(float x) {
    float r; asm("tanh.approx.f32 %0,%1;" : "=f"(r) : "f"(x)); return r;
}
__device__ __forceinline__ u64 f2ex2(u64 v) {
    float lo, hi; upk2(lo, hi, v); return pk2(ex2f(lo), ex2f(hi));
}
__device__ __forceinline__ u64 f2tanh(u64 v) {
    float lo, hi; upk2(lo, hi, v); return pk2(tanhf_a(lo), tanhf_a(hi));
}

__global__ __launch_bounds__(64)
void topo_kernel(const float* __restrict__ pillars,
                 const float* __restrict__ W1,   // [P][H]
                 const float* __restrict__ b1,
                 const float* __restrict__ W2,
                 const float* __restrict__ b2p,
                 const float* __restrict__ ln_g,
                 const float* __restrict__ ln_b,
                 const float* __restrict__ Wc,
                 const float* __restrict__ bcp,
                 float* __restrict__ out, int n)
{
    // per-h record: {w0,w0}{w1,w1}{w2,w2}{w3,w3}{w4,w4}{bh,bh}{w2h,w2h}{cs,cs} = 64B
    __shared__ __align__(16) float2 sw[NH * 8];
    __shared__ float sg[NP], sbe[NP], sWc[12];
    __shared__ float sb2, sbc;

    const int t = threadIdx.x;
    if (t < NH) {   // blockDim = 64 == NH: exact cover
        float w[NP]; float cn = 0.f;
        #pragma unroll
        for (int j = 0; j < NP; j++) { w[j] = W1[j * NH + t]; cn += w[j] * w[j]; }
        float w2h = W2[t], bh = b1[t];
        float cs = cn * w2h * 0.3989422804f;   // colnorm * W2 * 1/sqrt(2pi)
        float2* d = &sw[t * 8];
        #pragma unroll
        for (int j = 0; j < NP; j++) d[j] = make_float2(w[j], w[j]);
        d[5] = make_float2(bh, bh);
        d[6] = make_float2(w2h, w2h);
        d[7] = make_float2(cs, cs);
    }
    if (t < NP)  { sg[t] = ln_g[t]; sbe[t] = ln_b[t]; }
    if (t < 12)  sWc[t] = Wc[t];
    if (t == 0)  { sb2 = b2p[0]; sbc = bcp[0]; }
    __syncthreads();

    const int pairIdx = blockIdx.x * blockDim.x + t;
    const int i0 = 2 * pairIdx;
    if (i0 >= n) return;
    const int i1 = (i0 + 1 < n) ? (i0 + 1) : i0;   // tail: duplicate

    // --- load + sanitize ---
    float rawA[NP], rawB[NP], pA[NP], pB[NP];
    #pragma unroll
    for (int j = 0; j < NP; j++) {
        float va = pillars[i0 * NP + j];
        float vb = pillars[i1 * NP + j];
        rawA[j] = va; rawB[j] = vb;
        float ca = isnan(va) ? 0.5f : va;
        float cb = isnan(vb) ? 0.5f : vb;
        pA[j] = fminf(fmaxf(ca, 0.f), 1.f);
        pB[j] = fminf(fmaxf(cb, 0.f), 1.f);
    }

    // --- layernorm ---
    float xA[NP], xB[NP];
    {
        float mu = 0.f; for (int j = 0; j < NP; j++) mu += pA[j]; mu *= 0.2f;
        float var = 0.f; for (int j = 0; j < NP; j++) { float d = pA[j] - mu; var += d * d; } var *= 0.2f;
        float is = rsqrtf(var + 1e-5f);
        #pragma unroll
        for (int j = 0; j < NP; j++) xA[j] = (pA[j] - mu) * is * sg[j] + sbe[j];
    }
    {
        float mu = 0.f; for (int j = 0; j < NP; j++) mu += pB[j]; mu *= 0.2f;
        float var = 0.f; for (int j = 0; j < NP; j++) { float d = pB[j] - mu; var += d * d; } var *= 0.2f;
        float is = rsqrtf(var + 1e-5f);
        #pragma unroll
        for (int j = 0; j < NP; j++) xB[j] = (pB[j] - mu) * is * sg[j] + sbe[j];
    }

    u64 p2[NP], x2[NP];
    #pragma unroll
    for (int j = 0; j < NP; j++) { p2[j] = pk2(pA[j], pB[j]); x2[j] = pk2(xA[j], xB[j]); }

    // packed constants
    const u64 C_NHL2E = pk2(-0.72134752044f, -0.72134752044f); // -log2(e)/2
    const u64 C_IS2PI = pk2(0.3989422804f, 0.3989422804f);     // 1/sqrt(2pi)
    const u64 C_HALF  = pk2(0.5f, 0.5f);
    const u64 C_TWO   = pk2(2.0f, 2.0f);
    const u64 C_NEG1  = pk2(-1.0f, -1.0f);
    // Phi(z) ~= 0.5 + 0.5*tanh(z*(A + B*z^2)), A=1.5976/2, B=0.070565992/2
    const u64 C_PA    = pk2(0.7988f, 0.7988f);
    const u64 C_PB    = pk2(0.035282996f, 0.035282996f);

    u64 V2 = pk2(0.f, 0.f), tr2 = V2;
    u64 g2[NP] = {V2, V2, V2, V2, V2};

    const ulonglong2* sp = reinterpret_cast<const ulonglong2*>(sw);

    #pragma unroll 8
    for (int h = 0; h < NH; h++) {
        ulonglong2 q01 = sp[h * 4 + 0];   // {w0,w0},{w1,w1}
        ulonglong2 q23 = sp[h * 4 + 1];   // {w2,w2},{w3,w3}
        ulonglong2 q45 = sp[h * 4 + 2];   // {w4,w4},{bh,bh}
        ulonglong2 q67 = sp[h * 4 + 3];   // {w2h,w2h},{cs,cs}

        u64 z1 = f2fma(p2[0], q01.x, q45.y);
        z1 = f2fma(p2[1], q01.y, z1);
        z1 = f2fma(p2[2], q23.x, z1);
        z1 = f2fma(p2[3], q23.y, z1);
        z1 = f2fma(p2[4], q45.x, z1);

        u64 z2 = f2fma(x2[0], q01.x, q45.y);
        z2 = f2fma(x2[1], q01.y, z2);
        z2 = f2fma(x2[2], q23.x, z2);
        z2 = f2fma(x2[3], q23.y, z2);
        z2 = f2fma(x2[4], q45.x, z2);

        u64 sq1  = f2mul(z1, z1);
        u64 e1   = f2ex2(f2mul(sq1, C_NHL2E));    // exp(-z1^2/2)
        u64 phi1 = f2mul(e1, C_IS2PI);            // N(0,1) pdf at z1

        u64 sq2  = f2mul(z2, z2);
        u64 e2   = f2ex2(f2mul(sq2, C_NHL2E));    // exp(-z2^2/2)

        // Phi(z1) via tanh-cubic (|abs err| ~3e-4 incl tanh.approx)
        u64 inner = f2fma(sq1, C_PB, C_PA);
        u64 arg   = f2mul(z1, inner);
        u64 th    = f2tanh(arg);
        u64 Phi   = f2fma(C_HALF, th, C_HALF);

        // V += gelu(z1)*w2h
        u64 zPhi = f2mul(z1, Phi);
        V2 = f2fma(zPhi, q67.x, V2);

        // s = gelu'(z1)*w2h = (Phi + z1*phi1)*w2h
        u64 s = f2fma(z1, phi1, Phi);
        s = f2mul(s, q67.x);
        g2[0] = f2fma(q01.x, s, g2[0]);
        g2[1] = f2fma(q01.y, s, g2[1]);
        g2[2] = f2fma(q23.x, s, g2[2]);
        g2[3] = f2fma(q23.y, s, g2[3]);
        g2[4] = f2fma(q45.x, s, g2[4]);

        // tr += cs * e2 * (2 - z2^2)   (cs = colnorm*W2/sqrt(2pi))
        u64 tm = f2fma(sq2, C_NEG1, C_TWO);
        tm = f2mul(e2, tm);
        tr2 = f2fma(q67.y, tm, tr2);
    }

    // --- epilogue (scalar per sample) ---
    float Va, Vb, tra, trb, ga[NP], gb[NP];
    upk2(Va, Vb, V2); upk2(tra, trb, tr2);
    #pragma unroll
    for (int j = 0; j < NP; j++) upk2(ga[j], gb[j], g2[j]);
    Va += sb2; Vb += sb2;
    float ema = tra * 0.2f, emb = trb * 0.2f;

    {
        float ss = Va * Va + ema * ema;
        #pragma unroll
        for (int j = 0; j < NP; j++) ss += rawA[j] * rawA[j] + ga[j] * ga[j];
        float invn = 1.0f / fmaxf(sqrtf(ss), 1e-12f);
        float dot = 0.f;
        #pragma unroll
        for (int j = 0; j < NP; j++) dot += rawA[j] * sWc[j];
        #pragma unroll
        for (int j = 0; j < NP; j++) dot += ga[j] * sWc[NP + j];
        dot += Va * sWc[10] + ema * sWc[11];
        float logit = sbc + dot * invn;
        float prob = 1.0f / (1.0f + __expf(-logit));
        out[i0] = fminf(fmaxf(prob, 0.f), 1.f);
    }
    if (i0 + 1 < n) {
        float ss = Vb * Vb + emb * emb;
        #pragma unroll
        for (int j = 0; j < NP; j++) ss += rawB[j] * rawB[j] + gb[j] * gb[j];
        float invn = 1.0f / fmaxf(sqrtf(ss), 1e-12f);
        float dot = 0.f;
        #pragma unroll
        for (int j = 0; j < NP; j++) dot += rawB[j] * sWc[j];
        #pragma unroll
        for (int j = 0; j < NP; j++) dot += gb[j] * sWc[NP + j];
        dot += Vb * sWc[10] + emb * sWc[11];
        float logit = sbc + dot * invn;
        float prob = 1.0f / (1.0f + __expf(-logit));
        out[i0 + 1] = fminf(fmaxf(prob, 0.f), 1.f);
    }
}

extern "C" void kernel_launch(void* const* d_in, const int* in_sizes, int n_in,
                              void* d_out, int out_size) {
    const float* pillars = (const float*)d_in[0];
    const float* W1      = (const float*)d_in[1];
    const float* b1      = (const float*)d_in[2];
    const float* W2      = (const float*)d_in[3];
    const float* b2      = (const float*)d_in[4];
    const float* ln_g    = (const float*)d_in[5];
    const float* ln_b    = (const float*)d_in[6];
    const float* Wc      = (const float*)d_in[7];
    const float* bc      = (const float*)d_in[8];
    float* out = (float*)d_out;
    int n = out_size;
    int pairs = (n + 1) / 2;
    int threads = 64;
    int blocks = (pairs + threads - 1) / threads;
    topo_kernel<<<blocks, threads>>>(pillars, W1, b1, W2, b2, ln_g, ln_b, Wc, bc, out, n);
}